// round 1
// baseline (speedup 1.0000x reference)
#include <cuda_runtime.h>
#include <cuda_bf16.h>
#include <math.h>

// Problem constants
#define BATCH 32
#define TT    128          // time steps
#define HH    512          // hidden
#define VV    32000        // vocab
#define MM    (BATCH*TT)   // 4096 rows
#define G3H   (3*HH)       // 1536

// ---------------- device scratch (static, no allocation) ----------------
__device__ float g_x [MM * HH];     // gathered embeddings      [4096,512]
__device__ float g_xg[MM * G3H];    // input gate preact        [4096,1536]
__device__ float g_h [2 * BATCH * HH]; // double-buffered hidden
__device__ float g_hs[MM * HH];     // all hidden states (b-major: m=b*T+t)

// ---------------- kernel 1: teacher-forced embedding gather ----------------
__global__ void gather_kernel(const float* __restrict__ emb,
                              const int* __restrict__ target,
                              float* __restrict__ x)
{
    int m = blockIdx.x;          // 0..4095
    int b = m / TT;
    int t = m % TT;
    int tok = (t == 0) ? 1 : target[b * TT + t - 1];
    const float4* src = reinterpret_cast<const float4*>(emb + (size_t)tok * HH);
    float4* dst = reinterpret_cast<float4*>(x + (size_t)m * HH);
    dst[threadIdx.x] = src[threadIdx.x];   // 128 threads * float4 = 512 floats
}

// ---------------- kernel 2: fp32 SGEMM  C[M,N] = A[M,K] * B[N,K]^T + bias[N] --
// BM=BN=128, BK=16, 256 threads, 8x8 per-thread microtile.
#define BM 128
#define BN 128
#define BK 16

__global__ void __launch_bounds__(256)
sgemm_nt_bias(const float* __restrict__ A,
              const float* __restrict__ B,
              const float* __restrict__ bias,
              float* __restrict__ C,
              int M, int N, int K)
{
    __shared__ float As[BK][BM];
    __shared__ float Bs[BK][BN];

    int tid = threadIdx.x;
    int m0 = blockIdx.y * BM;
    int n0 = blockIdx.x * BN;

    int tm = (tid >> 4) * 8;    // 0..120
    int tn = (tid & 15) * 8;    // 0..120

    float acc[8][8];
#pragma unroll
    for (int i = 0; i < 8; ++i)
#pragma unroll
        for (int j = 0; j < 8; ++j) acc[i][j] = 0.f;

    for (int k0 = 0; k0 < K; k0 += BK) {
        // load tiles (each thread: 2 float4 of A, 2 float4 of B)
#pragma unroll
        for (int r = 0; r < 2; ++r) {
            int id  = tid + r * 256;     // 0..511
            int row = id >> 2;           // 0..127
            int c4  = id & 3;            // 0..3
            float4 va = *reinterpret_cast<const float4*>(
                A + (size_t)(m0 + row) * K + k0 + c4 * 4);
            As[c4*4+0][row] = va.x; As[c4*4+1][row] = va.y;
            As[c4*4+2][row] = va.z; As[c4*4+3][row] = va.w;
            float4 vb = *reinterpret_cast<const float4*>(
                B + (size_t)(n0 + row) * K + k0 + c4 * 4);
            Bs[c4*4+0][row] = vb.x; Bs[c4*4+1][row] = vb.y;
            Bs[c4*4+2][row] = vb.z; Bs[c4*4+3][row] = vb.w;
        }
        __syncthreads();

#pragma unroll
        for (int kk = 0; kk < BK; ++kk) {
            float a[8], bb[8];
            *reinterpret_cast<float4*>(&a[0])  = *reinterpret_cast<float4*>(&As[kk][tm]);
            *reinterpret_cast<float4*>(&a[4])  = *reinterpret_cast<float4*>(&As[kk][tm+4]);
            *reinterpret_cast<float4*>(&bb[0]) = *reinterpret_cast<float4*>(&Bs[kk][tn]);
            *reinterpret_cast<float4*>(&bb[4]) = *reinterpret_cast<float4*>(&Bs[kk][tn+4]);
#pragma unroll
            for (int i = 0; i < 8; ++i)
#pragma unroll
                for (int j = 0; j < 8; ++j)
                    acc[i][j] = fmaf(a[i], bb[j], acc[i][j]);
        }
        __syncthreads();
    }

    float bv[8];
#pragma unroll
    for (int j = 0; j < 8; ++j) bv[j] = bias[n0 + tn + j];

#pragma unroll
    for (int i = 0; i < 8; ++i) {
        float4 o0, o1;
        o0.x = acc[i][0] + bv[0]; o0.y = acc[i][1] + bv[1];
        o0.z = acc[i][2] + bv[2]; o0.w = acc[i][3] + bv[3];
        o1.x = acc[i][4] + bv[4]; o1.y = acc[i][5] + bv[5];
        o1.z = acc[i][6] + bv[6]; o1.w = acc[i][7] + bv[7];
        float* cp = C + (size_t)(m0 + tm + i) * N + n0 + tn;
        *reinterpret_cast<float4*>(cp)     = o0;
        *reinterpret_cast<float4*>(cp + 4) = o1;
    }
}

// ---------------- kernel 3: one GRU step ----------------
// grid 128 CTAs * 256 threads. CTA owns 4 hidden indices i0..i0+3, all 32 batches.
// warp w: i_local = w&3, khalf = w>>2 (k-split 2).
// h staged through smem in 4 chunks of 128 k (transposed, padded).
__device__ __forceinline__ float sigmoidf_(float x) {
    return 1.0f / (1.0f + expf(-x));
}

__global__ void __launch_bounds__(256)
gru_step_kernel(const float* __restrict__ h_prev,   // [32,512]
                float* __restrict__ h_next,         // [32,512]
                const float* __restrict__ xg,       // [4096,1536]
                const float* __restrict__ w_hh,     // [1536,512]
                const float* __restrict__ b_hh,     // [1536]
                float* __restrict__ hs,             // [4096,512]
                int t)
{
    __shared__ float h_s[128][33];        // chunk of h, transposed: h_s[k][b]
    __shared__ float red[4][3][32];       // partial sums from khalf=1 warps

    int tid  = threadIdx.x;
    int lane = tid & 31;                  // = batch b
    int w    = tid >> 5;                  // warp id 0..7
    int il   = w & 3;                     // i_local
    int kh   = w >> 2;                    // k-half
    int i0   = blockIdx.x * 4;
    int i    = i0 + il;

    float accr = 0.f, accz = 0.f, accn = 0.f;

    // loading map: b = tid>>3 (0..31), q = tid&7 ; each thread 4 float4 along k
    int lb = tid >> 3;
    int lq = tid & 7;

    for (int c = 0; c < 4; ++c) {
        // cooperative load of h chunk [c*128, c*128+128) transposed into smem
#pragma unroll
        for (int jj = 0; jj < 4; ++jj) {
            int kk = (lq + jj * 8) * 4;   // 0..124 step 4
            float4 v = *reinterpret_cast<const float4*>(
                h_prev + (size_t)lb * HH + c * 128 + kk);
            h_s[kk+0][lb] = v.x; h_s[kk+1][lb] = v.y;
            h_s[kk+2][lb] = v.z; h_s[kk+3][lb] = v.w;
        }
        __syncthreads();

        if ((c >> 1) == kh) {
            const float4* wr = reinterpret_cast<const float4*>(
                w_hh + (size_t)(i)          * HH + c * 128);
            const float4* wz = reinterpret_cast<const float4*>(
                w_hh + (size_t)(i + HH)     * HH + c * 128);
            const float4* wn = reinterpret_cast<const float4*>(
                w_hh + (size_t)(i + 2*HH)   * HH + c * 128);
#pragma unroll 8
            for (int k4 = 0; k4 < 32; ++k4) {
                float4 a = wr[k4];
                float4 d = wz[k4];
                float4 e = wn[k4];
                int kk = k4 * 4;
                float h0 = h_s[kk+0][lane];
                float h1 = h_s[kk+1][lane];
                float h2 = h_s[kk+2][lane];
                float h3 = h_s[kk+3][lane];
                accr = fmaf(a.x, h0, accr); accr = fmaf(a.y, h1, accr);
                accr = fmaf(a.z, h2, accr); accr = fmaf(a.w, h3, accr);
                accz = fmaf(d.x, h0, accz); accz = fmaf(d.y, h1, accz);
                accz = fmaf(d.z, h2, accz); accz = fmaf(d.w, h3, accz);
                accn = fmaf(e.x, h0, accn); accn = fmaf(e.y, h1, accn);
                accn = fmaf(e.z, h2, accn); accn = fmaf(e.w, h3, accn);
            }
        }
        __syncthreads();
    }

    // cross-khalf reduction via smem
    if (kh == 1) {
        red[il][0][lane] = accr;
        red[il][1][lane] = accz;
        red[il][2][lane] = accn;
    }
    __syncthreads();

    if (kh == 0) {
        accr += red[il][0][lane];
        accz += red[il][1][lane];
        accn += red[il][2][lane];

        int b = lane;
        float hr = accr + b_hh[i];
        float hz = accz + b_hh[i + HH];
        float hn = accn + b_hh[i + 2*HH];

        size_t mrow = (size_t)(b * TT + t);
        const float* xgp = xg + mrow * G3H;
        float xr = xgp[i];
        float xz = xgp[i + HH];
        float xn = xgp[i + 2*HH];

        float r = sigmoidf_(xr + hr);
        float z = sigmoidf_(xz + hz);
        float n = tanhf(xn + r * hn);
        float hp = h_prev[(size_t)b * HH + i];
        float hnew = (1.0f - z) * n + z * hp;

        h_next[(size_t)b * HH + i] = hnew;
        hs[mrow * HH + i] = hnew;
    }
}

// ---------------- launcher ----------------
extern "C" void kernel_launch(void* const* d_in, const int* in_sizes, int n_in,
                              void* d_out, int out_size)
{
    const float* emb    = (const float*)d_in[0];   // [32000,512]
    const float* w_ih   = (const float*)d_in[1];   // [1536,512]
    const float* w_hh   = (const float*)d_in[2];   // [1536,512]
    const float* b_ih   = (const float*)d_in[3];   // [1536]
    const float* b_hh   = (const float*)d_in[4];   // [1536]
    const float* b_out  = (const float*)d_in[5];   // [32000]
    const float* enc    = (const float*)d_in[6];   // [1,32,512]
    const int*   target = (const int*)  d_in[7];   // [32,128]
    float* out = (float*)d_out;                    // [32,128,32000]

    // resolve device-scratch addresses (pure queries; capture-safe)
    float *px, *pxg, *ph, *phs;
    cudaGetSymbolAddress((void**)&px,  g_x);
    cudaGetSymbolAddress((void**)&pxg, g_xg);
    cudaGetSymbolAddress((void**)&ph,  g_h);
    cudaGetSymbolAddress((void**)&phs, g_hs);

    // 1) gather teacher-forced embeddings
    gather_kernel<<<MM, 128>>>(emb, target, px);

    // 2) xg = x @ w_ih^T + b_ih   [4096,1536]
    {
        dim3 grid(G3H / BN, MM / BM);   // 12 x 32
        sgemm_nt_bias<<<grid, 256>>>(px, w_ih, b_ih, pxg, MM, G3H, HH);
    }

    // 3) sequential GRU scan: 128 step kernels
    for (int t = 0; t < TT; ++t) {
        const float* hp = (t == 0) ? enc : (ph + (size_t)(t & 1) * BATCH * HH);
        float* hn = ph + (size_t)((t + 1) & 1) * BATCH * HH;
        gru_step_kernel<<<128, 256>>>(hp, hn, pxg, w_hh, b_hh, phs, t);
    }

    // 4) logits = hs @ emb^T + b_out   [4096,32000]
    {
        dim3 grid(VV / BN, MM / BM);    // 250 x 32
        sgemm_nt_bias<<<grid, 256>>>(phs, emb, b_out, out, MM, VV, HH);
    }
}

// round 3
// speedup vs baseline: 1.4087x; 1.4087x over previous
#include <cuda_runtime.h>
#include <cuda_bf16.h>
#include <math.h>
#include <stdint.h>

// Problem constants
#define BATCH 32
#define TT    128          // time steps
#define HH    512          // hidden
#define VV    32000        // vocab
#define MM    (BATCH*TT)   // 4096 rows
#define G3H   (3*HH)       // 1536

// Logits GEMM (bf16-split) tiling
#define GBM 128
#define GBN 128
#define GBK 32
#define GKT 1536           // split-concat K
#define GNC (GKT/GBK)      // 48 chunks
#define PITCH 80           // smem row pitch bytes (64B data + 16B pad) -> conflict-free ldmatrix
#define ABYTES (GBM*PITCH) // 10240
#define BBYTES (GBN*PITCH) // 10240
#define BUFBYTES (ABYTES+BBYTES)

// ---------------- device scratch (static, no allocation) ----------------
__device__ __align__(256) float g_x [MM * HH];       // gathered embeddings [4096,512]
__device__ __align__(256) float g_xg[MM * G3H];      // input gate preact   [4096,1536]
__device__ __align__(256) float g_h [2 * BATCH * HH];// double-buffered hidden
__device__ __align__(256) float g_hs[MM * HH];       // hidden states (m = b*T+t)
__device__ __align__(256) __nv_bfloat16 g_a2[MM * GKT];   // [Ah|Al|Ah] of hs
__device__ __align__(256) __nv_bfloat16 g_b2[VV * GKT];   // [Bh|Bh|Bl] of emb

// =============================== PTX helpers ===============================
__device__ __forceinline__ uint32_t smem_u32(const void* p) {
    uint32_t r;
    asm("{ .reg .u64 t; cvta.to.shared.u64 t, %1; cvt.u32.u64 %0, t; }"
        : "=r"(r) : "l"(p));
    return r;
}
__device__ __forceinline__ void cp_async16(uint32_t dst, const void* src) {
    asm volatile("cp.async.cg.shared.global [%0], [%1], 16;\n"
                 :: "r"(dst), "l"(src));
}
__device__ __forceinline__ void cp_async_commit() {
    asm volatile("cp.async.commit_group;\n" ::: "memory");
}
__device__ __forceinline__ void cp_async_wait_all() {
    asm volatile("cp.async.wait_group 0;\n" ::: "memory");
}
__device__ __forceinline__ void ldsm_x4(uint32_t* r, uint32_t addr) {
    asm volatile("ldmatrix.sync.aligned.m8n8.x4.shared.b16 {%0,%1,%2,%3}, [%4];\n"
                 : "=r"(r[0]), "=r"(r[1]), "=r"(r[2]), "=r"(r[3]) : "r"(addr));
}
__device__ __forceinline__ void mma16816(float* c, const uint32_t* a, const uint32_t* b) {
    asm volatile(
        "mma.sync.aligned.m16n8k16.row.col.f32.bf16.bf16.f32 "
        "{%0,%1,%2,%3}, {%4,%5,%6,%7}, {%8,%9}, {%0,%1,%2,%3};\n"
        : "+f"(c[0]), "+f"(c[1]), "+f"(c[2]), "+f"(c[3])
        : "r"(a[0]), "r"(a[1]), "r"(a[2]), "r"(a[3]), "r"(b[0]), "r"(b[1]));
}

// ---------------- kernel 1: teacher-forced embedding gather ----------------
__global__ void gather_kernel(const float* __restrict__ emb,
                              const int* __restrict__ target,
                              float* __restrict__ x)
{
    int m = blockIdx.x;
    int b = m / TT;
    int t = m % TT;
    int tok = (t == 0) ? 1 : target[b * TT + t - 1];
    const float4* src = reinterpret_cast<const float4*>(emb + (size_t)tok * HH);
    float4* dst = reinterpret_cast<float4*>(x + (size_t)m * HH);
    dst[threadIdx.x] = src[threadIdx.x];
}

// ---------------- kernel 2: fp32 SGEMM (for xg)  C = A*B^T + bias ----------
#define BM 128
#define BN 128
#define BK 16

__global__ void __launch_bounds__(256)
sgemm_nt_bias(const float* __restrict__ A,
              const float* __restrict__ B,
              const float* __restrict__ bias,
              float* __restrict__ C,
              int M, int N, int K)
{
    __shared__ float As[BK][BM];
    __shared__ float Bs[BK][BN];

    int tid = threadIdx.x;
    int m0 = blockIdx.y * BM;
    int n0 = blockIdx.x * BN;

    int tm = (tid >> 4) * 8;
    int tn = (tid & 15) * 8;

    float acc[8][8];
#pragma unroll
    for (int i = 0; i < 8; ++i)
#pragma unroll
        for (int j = 0; j < 8; ++j) acc[i][j] = 0.f;

    for (int k0 = 0; k0 < K; k0 += BK) {
#pragma unroll
        for (int r = 0; r < 2; ++r) {
            int id  = tid + r * 256;
            int row = id >> 2;
            int c4  = id & 3;
            float4 va = *reinterpret_cast<const float4*>(
                A + (size_t)(m0 + row) * K + k0 + c4 * 4);
            As[c4*4+0][row] = va.x; As[c4*4+1][row] = va.y;
            As[c4*4+2][row] = va.z; As[c4*4+3][row] = va.w;
            float4 vb = *reinterpret_cast<const float4*>(
                B + (size_t)(n0 + row) * K + k0 + c4 * 4);
            Bs[c4*4+0][row] = vb.x; Bs[c4*4+1][row] = vb.y;
            Bs[c4*4+2][row] = vb.z; Bs[c4*4+3][row] = vb.w;
        }
        __syncthreads();

#pragma unroll
        for (int kk = 0; kk < BK; ++kk) {
            float a[8], bb[8];
            *reinterpret_cast<float4*>(&a[0])  = *reinterpret_cast<float4*>(&As[kk][tm]);
            *reinterpret_cast<float4*>(&a[4])  = *reinterpret_cast<float4*>(&As[kk][tm+4]);
            *reinterpret_cast<float4*>(&bb[0]) = *reinterpret_cast<float4*>(&Bs[kk][tn]);
            *reinterpret_cast<float4*>(&bb[4]) = *reinterpret_cast<float4*>(&Bs[kk][tn+4]);
#pragma unroll
            for (int i = 0; i < 8; ++i)
#pragma unroll
                for (int j = 0; j < 8; ++j)
                    acc[i][j] = fmaf(a[i], bb[j], acc[i][j]);
        }
        __syncthreads();
    }

    float bv[8];
#pragma unroll
    for (int j = 0; j < 8; ++j) bv[j] = bias[n0 + tn + j];

#pragma unroll
    for (int i = 0; i < 8; ++i) {
        float4 o0, o1;
        o0.x = acc[i][0] + bv[0]; o0.y = acc[i][1] + bv[1];
        o0.z = acc[i][2] + bv[2]; o0.w = acc[i][3] + bv[3];
        o1.x = acc[i][4] + bv[4]; o1.y = acc[i][5] + bv[5];
        o1.z = acc[i][6] + bv[6]; o1.w = acc[i][7] + bv[7];
        float* cp = C + (size_t)(m0 + tm + i) * N + n0 + tn;
        *reinterpret_cast<float4*>(cp)     = o0;
        *reinterpret_cast<float4*>(cp + 4) = o1;
    }
}

// ---------------- kernel 3: one GRU step (unchanged) ----------------
__device__ __forceinline__ float sigmoidf_(float x) {
    return 1.0f / (1.0f + expf(-x));
}

__global__ void __launch_bounds__(256)
gru_step_kernel(const float* __restrict__ h_prev,
                float* __restrict__ h_next,
                const float* __restrict__ xg,
                const float* __restrict__ w_hh,
                const float* __restrict__ b_hh,
                float* __restrict__ hs,
                int t)
{
    __shared__ float h_s[128][33];
    __shared__ float red[4][3][32];

    int tid  = threadIdx.x;
    int lane = tid & 31;
    int w    = tid >> 5;
    int il   = w & 3;
    int kh   = w >> 2;
    int i0   = blockIdx.x * 4;
    int i    = i0 + il;

    float accr = 0.f, accz = 0.f, accn = 0.f;

    int lb = tid >> 3;
    int lq = tid & 7;

    for (int c = 0; c < 4; ++c) {
#pragma unroll
        for (int jj = 0; jj < 4; ++jj) {
            int kk = (lq + jj * 8) * 4;
            float4 v = *reinterpret_cast<const float4*>(
                h_prev + (size_t)lb * HH + c * 128 + kk);
            h_s[kk+0][lb] = v.x; h_s[kk+1][lb] = v.y;
            h_s[kk+2][lb] = v.z; h_s[kk+3][lb] = v.w;
        }
        __syncthreads();

        if ((c >> 1) == kh) {
            const float4* wr = reinterpret_cast<const float4*>(
                w_hh + (size_t)(i)          * HH + c * 128);
            const float4* wz = reinterpret_cast<const float4*>(
                w_hh + (size_t)(i + HH)     * HH + c * 128);
            const float4* wn = reinterpret_cast<const float4*>(
                w_hh + (size_t)(i + 2*HH)   * HH + c * 128);
#pragma unroll 8
            for (int k4 = 0; k4 < 32; ++k4) {
                float4 a = wr[k4];
                float4 d = wz[k4];
                float4 e = wn[k4];
                int kk = k4 * 4;
                float h0 = h_s[kk+0][lane];
                float h1 = h_s[kk+1][lane];
                float h2 = h_s[kk+2][lane];
                float h3 = h_s[kk+3][lane];
                accr = fmaf(a.x, h0, accr); accr = fmaf(a.y, h1, accr);
                accr = fmaf(a.z, h2, accr); accr = fmaf(a.w, h3, accr);
                accz = fmaf(d.x, h0, accz); accz = fmaf(d.y, h1, accz);
                accz = fmaf(d.z, h2, accz); accz = fmaf(d.w, h3, accz);
                accn = fmaf(e.x, h0, accn); accn = fmaf(e.y, h1, accn);
                accn = fmaf(e.z, h2, accn); accn = fmaf(e.w, h3, accn);
            }
        }
        __syncthreads();
    }

    if (kh == 1) {
        red[il][0][lane] = accr;
        red[il][1][lane] = accz;
        red[il][2][lane] = accn;
    }
    __syncthreads();

    if (kh == 0) {
        accr += red[il][0][lane];
        accz += red[il][1][lane];
        accn += red[il][2][lane];

        int b = lane;
        float hr = accr + b_hh[i];
        float hz = accz + b_hh[i + HH];
        float hn = accn + b_hh[i + 2*HH];

        size_t mrow = (size_t)(b * TT + t);
        const float* xgp = xg + mrow * G3H;
        float xr = xgp[i];
        float xz = xgp[i + HH];
        float xn = xgp[i + 2*HH];

        float r = sigmoidf_(xr + hr);
        float z = sigmoidf_(xz + hz);
        float n = tanhf(xn + r * hn);
        float hp = h_prev[(size_t)b * HH + i];
        float hnew = (1.0f - z) * n + z * hp;

        h_next[(size_t)b * HH + i] = hnew;
        hs[mrow * HH + i] = hnew;
    }
}

// ---------------- kernel 4: split emb -> [Bh | Bh | Bl] bf16 ----------------
__global__ void __launch_bounds__(128)
split_emb_kernel(const float* __restrict__ emb, __nv_bfloat16* __restrict__ b2)
{
    int row = blockIdx.x;              // 0..31999
    const float* src = emb + (size_t)row * HH;
    __nv_bfloat16* dst = b2 + (size_t)row * GKT;
#pragma unroll
    for (int j = 0; j < 4; ++j) {
        int k = threadIdx.x + j * 128;
        float v = src[k];
        __nv_bfloat16 hi = __float2bfloat16(v);
        float rem = v - __bfloat162float(hi);
        __nv_bfloat16 lo = __float2bfloat16(rem);
        dst[k]          = hi;
        dst[k + HH]     = hi;
        dst[k + 2*HH]   = lo;
    }
}

// ---------------- kernel 5: split hs -> [Ah | Al | Ah] bf16 ----------------
__global__ void __launch_bounds__(128)
split_hs_kernel(const float* __restrict__ hs, __nv_bfloat16* __restrict__ a2)
{
    int row = blockIdx.x;              // 0..4095
    const float* src = hs + (size_t)row * HH;
    __nv_bfloat16* dst = a2 + (size_t)row * GKT;
#pragma unroll
    for (int j = 0; j < 4; ++j) {
        int k = threadIdx.x + j * 128;
        float v = src[k];
        __nv_bfloat16 hi = __float2bfloat16(v);
        float rem = v - __bfloat162float(hi);
        __nv_bfloat16 lo = __float2bfloat16(rem);
        dst[k]          = hi;
        dst[k + HH]     = lo;
        dst[k + 2*HH]   = hi;
    }
}

// ---------------- kernel 6: mma.sync bf16 split GEMM (logits) ----------------
// C[4096,32000] = A2[4096,1536] * B2[32000,1536]^T + bias, fp32 accumulate.
// BM=BN=128, BK=32, 256 threads, warps 4(m) x 2(n), warp tile 32x64.
// smem rows padded to 80B -> conflict-free ldmatrix.

__device__ __forceinline__ void gemm_load_tile(
    uint32_t sa, uint32_t sbm, int m0, int n0, int chunk, int tid,
    const __nv_bfloat16* __restrict__ A, const __nv_bfloat16* __restrict__ B)
{
    // A: 128 rows x 64B = 512 x 16B chunks, 2 per thread
#pragma unroll
    for (int r = 0; r < 2; ++r) {
        int c = tid + r * 256;
        int row = c >> 2;
        int q   = c & 3;
        cp_async16(sa + row * PITCH + q * 16,
                   A + (size_t)(m0 + row) * GKT + chunk * GBK + q * 8);
    }
    // B: same shape
#pragma unroll
    for (int r = 0; r < 2; ++r) {
        int c = tid + r * 256;
        int row = c >> 2;
        int q   = c & 3;
        cp_async16(sbm + row * PITCH + q * 16,
                   B + (size_t)(n0 + row) * GKT + chunk * GBK + q * 8);
    }
    cp_async_commit();
}

__global__ void __launch_bounds__(256)
gemm_bf16_mma(const __nv_bfloat16* __restrict__ A,
              const __nv_bfloat16* __restrict__ B,
              const float* __restrict__ bias,
              float* __restrict__ C)
{
    __shared__ __align__(128) char smem[2 * BUFBYTES];

    const int tid  = threadIdx.x;
    const int lane = tid & 31;
    const int wid  = tid >> 5;
    const int wm   = wid & 3;        // 0..3 (m)
    const int wn   = wid >> 2;       // 0..1 (n)
    const int m0 = blockIdx.x * GBM; // 32 m-tiles (fast dim -> A L2 reuse)
    const int n0 = blockIdx.y * GBN; // 250 n-tiles

    const uint32_t sb = smem_u32(smem);
    const uint32_t sa0 = sb;
    const uint32_t sb0 = sb + ABYTES;

    float acc[2][8][4];
#pragma unroll
    for (int i = 0; i < 2; ++i)
#pragma unroll
        for (int j = 0; j < 8; ++j)
#pragma unroll
            for (int k = 0; k < 4; ++k) acc[i][j][k] = 0.f;

    // prologue: chunk 0 -> buf 0
    gemm_load_tile(sa0, sb0, m0, n0, 0, tid, A, B);

    // precomputed ldmatrix lane offsets
    const uint32_t a_lane_off = (uint32_t)(lane & 15) * PITCH + (uint32_t)(lane >> 4) * 16;
    const uint32_t b_lane_off = (uint32_t)(lane & 7)  * PITCH + (uint32_t)(lane >> 3) * 16;

    for (int c = 0; c < GNC; ++c) {
        int cur = c & 1;
        uint32_t sa = sb + cur * BUFBYTES;
        uint32_t sbm = sa + ABYTES;

        cp_async_wait_all();
        __syncthreads();

        if (c + 1 < GNC) {
            int nxt = (c + 1) & 1;
            gemm_load_tile(sb + nxt * BUFBYTES, sb + nxt * BUFBYTES + ABYTES,
                           m0, n0, c + 1, tid, A, B);
        }

        // B fragments: 8 n-tiles, x4 covers k0..31 (regs: k0-7,k8-15,k16-23,k24-31)
        uint32_t bf[8][4];
#pragma unroll
        for (int nt = 0; nt < 8; ++nt) {
            uint32_t addr = sbm + (uint32_t)(wn * 64 + nt * 8) * PITCH + b_lane_off;
            ldsm_x4(bf[nt], addr);
        }

#pragma unroll
        for (int ks = 0; ks < 2; ++ks) {
#pragma unroll
            for (int mt = 0; mt < 2; ++mt) {
                uint32_t af[4];
                uint32_t addr = sa + (uint32_t)(wm * 32 + mt * 16) * PITCH
                                + (uint32_t)(ks * 2) * 16 + a_lane_off;
                ldsm_x4(af, addr);
#pragma unroll
                for (int nt = 0; nt < 8; ++nt)
                    mma16816(acc[mt][nt], af, &bf[nt][ks * 2]);
            }
        }
        __syncthreads();
    }

    // epilogue: write C + bias
    const int col_base = n0 + wn * 64 + 2 * (lane & 3);
    const int row_base = m0 + wm * 32 + (lane >> 2);
#pragma unroll
    for (int mt = 0; mt < 2; ++mt) {
#pragma unroll
        for (int half = 0; half < 2; ++half) {
            int row = row_base + mt * 16 + half * 8;
            float* cr = C + (size_t)row * VV;
#pragma unroll
            for (int nt = 0; nt < 8; ++nt) {
                int col = col_base + nt * 8;
                float2 o;
                o.x = acc[mt][nt][half * 2 + 0] + bias[col];
                o.y = acc[mt][nt][half * 2 + 1] + bias[col + 1];
                *reinterpret_cast<float2*>(cr + col) = o;
            }
        }
    }
}

// ---------------- launcher ----------------
extern "C" void kernel_launch(void* const* d_in, const int* in_sizes, int n_in,
                              void* d_out, int out_size)
{
    const float* emb    = (const float*)d_in[0];   // [32000,512]
    const float* w_ih   = (const float*)d_in[1];   // [1536,512]
    const float* w_hh   = (const float*)d_in[2];   // [1536,512]
    const float* b_ih   = (const float*)d_in[3];   // [1536]
    const float* b_hh   = (const float*)d_in[4];   // [1536]
    const float* b_out  = (const float*)d_in[5];   // [32000]
    const float* enc    = (const float*)d_in[6];   // [1,32,512]
    const int*   target = (const int*)  d_in[7];   // [32,128]
    float* out = (float*)d_out;                    // [32,128,32000]

    float *px, *pxg, *ph, *phs;
    __nv_bfloat16 *pa2, *pb2;
    cudaGetSymbolAddress((void**)&px,  g_x);
    cudaGetSymbolAddress((void**)&pxg, g_xg);
    cudaGetSymbolAddress((void**)&ph,  g_h);
    cudaGetSymbolAddress((void**)&phs, g_hs);
    cudaGetSymbolAddress((void**)&pa2, g_a2);
    cudaGetSymbolAddress((void**)&pb2, g_b2);

    // 1) gather teacher-forced embeddings
    gather_kernel<<<MM, 128>>>(emb, target, px);

    // 1b) split embedding into bf16 hi/lo concat (independent of scan)
    split_emb_kernel<<<VV, 128>>>(emb, pb2);

    // 2) xg = x @ w_ih^T + b_ih   [4096,1536]
    {
        dim3 grid(G3H / BN, MM / BM);
        sgemm_nt_bias<<<grid, 256>>>(px, w_ih, b_ih, pxg, MM, G3H, HH);
    }

    // 3) sequential GRU scan
    for (int t = 0; t < TT; ++t) {
        const float* hp = (t == 0) ? enc : (ph + (size_t)(t & 1) * BATCH * HH);
        float* hn = ph + (size_t)((t + 1) & 1) * BATCH * HH;
        gru_step_kernel<<<128, 256>>>(hp, hn, pxg, w_hh, b_hh, phs, t);
    }

    // 3b) split hidden states into bf16 hi/lo concat
    split_hs_kernel<<<MM, 128>>>(phs, pa2);

    // 4) logits = hs @ emb^T + b_out via mma.sync bf16-split GEMM
    {
        dim3 grid(MM / GBM, VV / GBN);   // (32, 250)
        gemm_bf16_mma<<<grid, 256>>>(pa2, pb2, b_out, out);
    }
}

// round 4
// speedup vs baseline: 2.6671x; 1.8933x over previous
#include <cuda_runtime.h>
#include <cuda_fp16.h>
#include <math.h>
#include <stdint.h>

// Problem constants
#define BATCH 32
#define TT    128          // time steps
#define HH    512          // hidden
#define VV    32000        // vocab
#define MM    (BATCH*TT)   // 4096 rows
#define G3H   (3*HH)       // 1536

// Logits GEMM (fp16 2-split) tiling
#define GBM 128
#define GBN 128
#define GBK 32
#define AKT 1024           // A split-concat K  [Ah|Al]
#define BKT 512            // B stored once (Bh)
#define GNC (AKT/GBK)      // 32 chunks (B chunk = c & 15)
#define PITCH 80           // smem row pitch bytes (64B data + 16B pad)
#define ABYTES (GBM*PITCH)
#define BBYTES (GBN*PITCH)
#define BUFBYTES (ABYTES+BBYTES)

#define SCAN_CTAS 128

// ---------------- device scratch (static, no allocation) ----------------
__device__ __align__(256) float g_x [MM * HH];        // gathered embeddings
__device__ __align__(256) float g_xg[MM * G3H];       // input gate preact
__device__ __align__(256) float g_h [2 * BATCH * HH]; // double-buffered hidden
__device__ __align__(256) __half g_a2[MM * AKT];      // [Ah|Al] of hidden states
__device__ __align__(256) __half g_b2[VV * BKT];      // Bh of emb
__device__ unsigned g_bar_cnt;
__device__ unsigned g_bar_gen;

// =============================== PTX helpers ===============================
__device__ __forceinline__ uint32_t smem_u32(const void* p) {
    uint32_t r;
    asm("{ .reg .u64 t; cvta.to.shared.u64 t, %1; cvt.u32.u64 %0, t; }"
        : "=r"(r) : "l"(p));
    return r;
}
__device__ __forceinline__ void cp_async16(uint32_t dst, const void* src) {
    asm volatile("cp.async.cg.shared.global [%0], [%1], 16;\n"
                 :: "r"(dst), "l"(src));
}
__device__ __forceinline__ void cp_async_commit() {
    asm volatile("cp.async.commit_group;\n" ::: "memory");
}
__device__ __forceinline__ void cp_async_wait_all() {
    asm volatile("cp.async.wait_group 0;\n" ::: "memory");
}
__device__ __forceinline__ void ldsm_x4(uint32_t* r, uint32_t addr) {
    asm volatile("ldmatrix.sync.aligned.m8n8.x4.shared.b16 {%0,%1,%2,%3}, [%4];\n"
                 : "=r"(r[0]), "=r"(r[1]), "=r"(r[2]), "=r"(r[3]) : "r"(addr));
}
__device__ __forceinline__ void mma16816(float* c, const uint32_t* a, const uint32_t* b) {
    asm volatile(
        "mma.sync.aligned.m16n8k16.row.col.f32.f16.f16.f32 "
        "{%0,%1,%2,%3}, {%4,%5,%6,%7}, {%8,%9}, {%0,%1,%2,%3};\n"
        : "+f"(c[0]), "+f"(c[1]), "+f"(c[2]), "+f"(c[3])
        : "r"(a[0]), "r"(a[1]), "r"(a[2]), "r"(a[3]), "r"(b[0]), "r"(b[1]));
}

// ---------------- kernel 1: teacher-forced embedding gather ----------------
__global__ void gather_kernel(const float* __restrict__ emb,
                              const int* __restrict__ target,
                              float* __restrict__ x)
{
    int m = blockIdx.x;
    int b = m / TT;
    int t = m % TT;
    int tok = (t == 0) ? 1 : target[b * TT + t - 1];
    const float4* src = reinterpret_cast<const float4*>(emb + (size_t)tok * HH);
    float4* dst = reinterpret_cast<float4*>(x + (size_t)m * HH);
    dst[threadIdx.x] = src[threadIdx.x];
}

// ---------------- kernel 2: fp32 SGEMM (for xg)  C = A*B^T + bias ----------
#define BM 128
#define BN 128
#define BK 16

__global__ void __launch_bounds__(256)
sgemm_nt_bias(const float* __restrict__ A,
              const float* __restrict__ B,
              const float* __restrict__ bias,
              float* __restrict__ C,
              int M, int N, int K)
{
    __shared__ float As[BK][BM];
    __shared__ float Bs[BK][BN];

    int tid = threadIdx.x;
    int m0 = blockIdx.y * BM;
    int n0 = blockIdx.x * BN;

    int tm = (tid >> 4) * 8;
    int tn = (tid & 15) * 8;

    float acc[8][8];
#pragma unroll
    for (int i = 0; i < 8; ++i)
#pragma unroll
        for (int j = 0; j < 8; ++j) acc[i][j] = 0.f;

    for (int k0 = 0; k0 < K; k0 += BK) {
#pragma unroll
        for (int r = 0; r < 2; ++r) {
            int id  = tid + r * 256;
            int row = id >> 2;
            int c4  = id & 3;
            float4 va = *reinterpret_cast<const float4*>(
                A + (size_t)(m0 + row) * K + k0 + c4 * 4);
            As[c4*4+0][row] = va.x; As[c4*4+1][row] = va.y;
            As[c4*4+2][row] = va.z; As[c4*4+3][row] = va.w;
            float4 vb = *reinterpret_cast<const float4*>(
                B + (size_t)(n0 + row) * K + k0 + c4 * 4);
            Bs[c4*4+0][row] = vb.x; Bs[c4*4+1][row] = vb.y;
            Bs[c4*4+2][row] = vb.z; Bs[c4*4+3][row] = vb.w;
        }
        __syncthreads();

#pragma unroll
        for (int kk = 0; kk < BK; ++kk) {
            float a[8], bb[8];
            *reinterpret_cast<float4*>(&a[0])  = *reinterpret_cast<float4*>(&As[kk][tm]);
            *reinterpret_cast<float4*>(&a[4])  = *reinterpret_cast<float4*>(&As[kk][tm+4]);
            *reinterpret_cast<float4*>(&bb[0]) = *reinterpret_cast<float4*>(&Bs[kk][tn]);
            *reinterpret_cast<float4*>(&bb[4]) = *reinterpret_cast<float4*>(&Bs[kk][tn+4]);
#pragma unroll
            for (int i = 0; i < 8; ++i)
#pragma unroll
                for (int j = 0; j < 8; ++j)
                    acc[i][j] = fmaf(a[i], bb[j], acc[i][j]);
        }
        __syncthreads();
    }

    float bv[8];
#pragma unroll
    for (int j = 0; j < 8; ++j) bv[j] = bias[n0 + tn + j];

#pragma unroll
    for (int i = 0; i < 8; ++i) {
        float4 o0, o1;
        o0.x = acc[i][0] + bv[0]; o0.y = acc[i][1] + bv[1];
        o0.z = acc[i][2] + bv[2]; o0.w = acc[i][3] + bv[3];
        o1.x = acc[i][4] + bv[4]; o1.y = acc[i][5] + bv[5];
        o1.z = acc[i][6] + bv[6]; o1.w = acc[i][7] + bv[7];
        float* cp = C + (size_t)(m0 + tm + i) * N + n0 + tn;
        *reinterpret_cast<float4*>(cp)     = o0;
        *reinterpret_cast<float4*>(cp + 4) = o1;
    }
}

// ---------------- kernel 3: persistent GRU scan ----------------
__device__ __forceinline__ float sigmoidf_(float x) {
    return 1.0f / (1.0f + expf(-x));
}

__device__ __forceinline__ void grid_barrier() {
    __syncthreads();
    if (threadIdx.x == 0) {
        __threadfence();
        unsigned gen = *((volatile unsigned*)&g_bar_gen);
        if (atomicAdd(&g_bar_cnt, 1u) == SCAN_CTAS - 1) {
            *((volatile unsigned*)&g_bar_cnt) = 0;
            __threadfence();
            atomicAdd(&g_bar_gen, 1u);
        } else {
            while (*((volatile unsigned*)&g_bar_gen) == gen) { }
        }
        __threadfence();
    }
    __syncthreads();
}

// grid 128 CTAs x 256 threads; CTA owns 4 hidden indices for all 32 batches.
// SMEM: w_s [12][512] f32 (24KB), h_T [512][33] f32 (67.6KB), red [12][32] (1.5KB)
__global__ void __launch_bounds__(256)
gru_scan_kernel(const float* __restrict__ enc,
                const float* __restrict__ xg,
                const float* __restrict__ w_hh,
                const float* __restrict__ b_hh,
                __half* __restrict__ a2,
                float* __restrict__ hbuf)
{
    extern __shared__ float sm[];
    float* w_s = sm;                  // 6144 floats
    float* h_T = sm + 6144;           // 16896 floats
    float* red = sm + 6144 + 16896;   // 384 floats

    const int tid  = threadIdx.x;
    const int lane = tid & 31;
    const int w    = tid >> 5;
    const int il   = w & 3;
    const int kh   = w >> 2;
    const int i0   = blockIdx.x * 4;
    const int i    = i0 + il;

    // load this CTA's 12 w_hh rows (gate-major) into smem
#pragma unroll
    for (int j = 0; j < 6; ++j) {
        int f   = tid + j * 256;       // float4 index 0..1535
        int row = f >> 7;              // 0..11
        int q   = f & 127;
        int g   = row >> 2, ii = row & 3;
        float4 v = *reinterpret_cast<const float4*>(
            w_hh + (size_t)(g * HH + i0 + ii) * HH + q * 4);
        *reinterpret_cast<float4*>(w_s + (size_t)row * HH + q * 4) = v;
    }
    const float br = b_hh[i];
    const float bz = b_hh[i + HH];
    const float bn = b_hh[i + 2*HH];

    const int lb = tid >> 3, lq = tid & 7;

    for (int t = 0; t < TT; ++t) {
        const float* hp = (t == 0) ? enc
                                   : hbuf + (size_t)(t & 1) * BATCH * HH;
        // stage h transposed into smem: h_T[k][b]
#pragma unroll
        for (int j = 0; j < 16; ++j) {
            int k4 = (lq + j * 8) * 4;
            float4 v = *reinterpret_cast<const float4*>(hp + (size_t)lb * HH + k4);
            h_T[(k4+0)*33 + lb] = v.x;
            h_T[(k4+1)*33 + lb] = v.y;
            h_T[(k4+2)*33 + lb] = v.z;
            h_T[(k4+3)*33 + lb] = v.w;
        }
        __syncthreads();

        float accr = 0.f, accz = 0.f, accn = 0.f;
        {
            const float4* wr4 = reinterpret_cast<const float4*>(w_s + (0*4+il)*HH) + kh*64;
            const float4* wz4 = reinterpret_cast<const float4*>(w_s + (1*4+il)*HH) + kh*64;
            const float4* wn4 = reinterpret_cast<const float4*>(w_s + (2*4+il)*HH) + kh*64;
            const float* hb = h_T + (size_t)(kh*256)*33 + lane;
#pragma unroll 8
            for (int k4 = 0; k4 < 64; ++k4) {
                float4 a = wr4[k4], d = wz4[k4], e = wn4[k4];
                const float* hq = hb + k4*4*33;
                float h0 = hq[0], h1 = hq[33], h2 = hq[66], h3 = hq[99];
                accr = fmaf(a.x,h0,accr); accr = fmaf(a.y,h1,accr);
                accr = fmaf(a.z,h2,accr); accr = fmaf(a.w,h3,accr);
                accz = fmaf(d.x,h0,accz); accz = fmaf(d.y,h1,accz);
                accz = fmaf(d.z,h2,accz); accz = fmaf(d.w,h3,accz);
                accn = fmaf(e.x,h0,accn); accn = fmaf(e.y,h1,accn);
                accn = fmaf(e.z,h2,accn); accn = fmaf(e.w,h3,accn);
            }
        }
        if (kh == 1) {
            red[(il*3+0)*32 + lane] = accr;
            red[(il*3+1)*32 + lane] = accz;
            red[(il*3+2)*32 + lane] = accn;
        }
        __syncthreads();
        if (kh == 0) {
            accr += red[(il*3+0)*32 + lane];
            accz += red[(il*3+1)*32 + lane];
            accn += red[(il*3+2)*32 + lane];

            int b = lane;
            size_t mrow = (size_t)b * TT + t;
            const float* xgp = xg + mrow * G3H;
            float r  = sigmoidf_(xgp[i]        + accr + br);
            float z  = sigmoidf_(xgp[i +   HH] + accz + bz);
            float hn = accn + bn;
            float n  = tanhf(xgp[i + 2*HH] + r * hn);
            float hprev = h_T[i*33 + b];
            float hnew = (1.0f - z) * n + z * hprev;

            hbuf[(size_t)((t+1)&1)*BATCH*HH + (size_t)b*HH + i] = hnew;
            __half hi16 = __float2half(hnew);
            float rem = hnew - __half2float(hi16);
            a2[mrow * AKT + i]       = hi16;
            a2[mrow * AKT + HH + i]  = __float2half(rem);
        }
        grid_barrier();
    }
}

// ---------------- kernel 4: emb -> fp16 Bh (K=512) ----------------
__global__ void __launch_bounds__(128)
split_emb_kernel(const float* __restrict__ emb, __half* __restrict__ b2)
{
    int row = blockIdx.x;              // 0..31999
    const float* src = emb + (size_t)row * HH;
    __half* dst = b2 + (size_t)row * BKT;
#pragma unroll
    for (int j = 0; j < 4; ++j) {
        int k = threadIdx.x + j * 128;
        dst[k] = __float2half(src[k]);
    }
}

// ---------------- kernel 5: mma.sync fp16 2-split GEMM (logits) -------------
// C[4096,32000] = A2[4096,1024] * Bh[32000,512](chunks repeated) + bias.
__device__ __forceinline__ void gemm_load_tile(
    uint32_t sa, uint32_t sbm, int m0, int n0, int chunk, int tid,
    const __half* __restrict__ A, const __half* __restrict__ B)
{
    int bchunk = chunk & 15;   // B has K=512; both A halves multiply Bh
#pragma unroll
    for (int r = 0; r < 2; ++r) {
        int c = tid + r * 256;
        int row = c >> 2;
        int q   = c & 3;
        cp_async16(sa + row * PITCH + q * 16,
                   A + (size_t)(m0 + row) * AKT + chunk * GBK + q * 8);
    }
#pragma unroll
    for (int r = 0; r < 2; ++r) {
        int c = tid + r * 256;
        int row = c >> 2;
        int q   = c & 3;
        cp_async16(sbm + row * PITCH + q * 16,
                   B + (size_t)(n0 + row) * BKT + bchunk * GBK + q * 8);
    }
    cp_async_commit();
}

__global__ void __launch_bounds__(256)
gemm_fp16_mma(const __half* __restrict__ A,
              const __half* __restrict__ B,
              const float* __restrict__ bias,
              float* __restrict__ C)
{
    __shared__ __align__(128) char smem[2 * BUFBYTES];

    const int tid  = threadIdx.x;
    const int lane = tid & 31;
    const int wid  = tid >> 5;
    const int wm   = wid & 3;
    const int wn   = wid >> 2;
    const int m0 = blockIdx.x * GBM;   // 32 m-tiles (fast dim -> A L2 reuse)
    const int n0 = blockIdx.y * GBN;   // 250 n-tiles

    const uint32_t sb = smem_u32(smem);

    float acc[2][8][4];
#pragma unroll
    for (int i = 0; i < 2; ++i)
#pragma unroll
        for (int j = 0; j < 8; ++j)
#pragma unroll
            for (int k = 0; k < 4; ++k) acc[i][j][k] = 0.f;

    gemm_load_tile(sb, sb + ABYTES, m0, n0, 0, tid, A, B);

    const uint32_t a_lane_off = (uint32_t)(lane & 15) * PITCH + (uint32_t)(lane >> 4) * 16;
    const uint32_t b_lane_off = (uint32_t)(lane & 7)  * PITCH + (uint32_t)(lane >> 3) * 16;

    for (int c = 0; c < GNC; ++c) {
        int cur = c & 1;
        uint32_t sa  = sb + cur * BUFBYTES;
        uint32_t sbm = sa + ABYTES;

        cp_async_wait_all();
        __syncthreads();

        if (c + 1 < GNC) {
            int nxt = (c + 1) & 1;
            gemm_load_tile(sb + nxt * BUFBYTES, sb + nxt * BUFBYTES + ABYTES,
                           m0, n0, c + 1, tid, A, B);
        }

        uint32_t bf[8][4];
#pragma unroll
        for (int nt = 0; nt < 8; ++nt) {
            uint32_t addr = sbm + (uint32_t)(wn * 64 + nt * 8) * PITCH + b_lane_off;
            ldsm_x4(bf[nt], addr);
        }

#pragma unroll
        for (int ks = 0; ks < 2; ++ks) {
#pragma unroll
            for (int mt = 0; mt < 2; ++mt) {
                uint32_t af[4];
                uint32_t addr = sa + (uint32_t)(wm * 32 + mt * 16) * PITCH
                                + (uint32_t)(ks * 2) * 16 + a_lane_off;
                ldsm_x4(af, addr);
#pragma unroll
                for (int nt = 0; nt < 8; ++nt)
                    mma16816(acc[mt][nt], af, &bf[nt][ks * 2]);
            }
        }
        __syncthreads();
    }

    const int col_base = n0 + wn * 64 + 2 * (lane & 3);
    const int row_base = m0 + wm * 32 + (lane >> 2);
#pragma unroll
    for (int mt = 0; mt < 2; ++mt) {
#pragma unroll
        for (int half = 0; half < 2; ++half) {
            int row = row_base + mt * 16 + half * 8;
            float* cr = C + (size_t)row * VV;
#pragma unroll
            for (int nt = 0; nt < 8; ++nt) {
                int col = col_base + nt * 8;
                float2 o;
                o.x = acc[mt][nt][half * 2 + 0] + bias[col];
                o.y = acc[mt][nt][half * 2 + 1] + bias[col + 1];
                *reinterpret_cast<float2*>(cr + col) = o;
            }
        }
    }
}

// ---------------- launcher ----------------
extern "C" void kernel_launch(void* const* d_in, const int* in_sizes, int n_in,
                              void* d_out, int out_size)
{
    const float* emb    = (const float*)d_in[0];   // [32000,512]
    const float* w_ih   = (const float*)d_in[1];   // [1536,512]
    const float* w_hh   = (const float*)d_in[2];   // [1536,512]
    const float* b_ih   = (const float*)d_in[3];   // [1536]
    const float* b_hh   = (const float*)d_in[4];   // [1536]
    const float* b_out  = (const float*)d_in[5];   // [32000]
    const float* enc    = (const float*)d_in[6];   // [1,32,512]
    const int*   target = (const int*)  d_in[7];   // [32,128]
    float* out = (float*)d_out;                    // [32,128,32000]

    float *px, *pxg, *ph;
    __half *pa2, *pb2;
    cudaGetSymbolAddress((void**)&px,  g_x);
    cudaGetSymbolAddress((void**)&pxg, g_xg);
    cudaGetSymbolAddress((void**)&ph,  g_h);
    cudaGetSymbolAddress((void**)&pa2, g_a2);
    cudaGetSymbolAddress((void**)&pb2, g_b2);

    const int scan_smem = (6144 + 16896 + 384) * 4;   // 93696 B
    cudaFuncSetAttribute(gru_scan_kernel,
                         cudaFuncAttributeMaxDynamicSharedMemorySize, scan_smem);

    // 1) gather teacher-forced embeddings
    gather_kernel<<<MM, 128>>>(emb, target, px);

    // 1b) emb -> fp16 Bh
    split_emb_kernel<<<VV, 128>>>(emb, pb2);

    // 2) xg = x @ w_ih^T + b_ih   [4096,1536]  (fp32)
    {
        dim3 grid(G3H / BN, MM / BM);
        sgemm_nt_bias<<<grid, 256>>>(px, w_ih, b_ih, pxg, MM, G3H, HH);
    }

    // 3) persistent GRU scan (writes fp16 [Ah|Al] directly)
    gru_scan_kernel<<<SCAN_CTAS, 256, scan_smem>>>(enc, pxg, w_hh, b_hh, pa2, ph);

    // 4) logits = hs @ emb^T + b_out via fp16 2-split mma GEMM
    {
        dim3 grid(MM / GBM, VV / GBN);   // (32, 250)
        gemm_fp16_mma<<<grid, 256>>>(pa2, pb2, b_out, out);
    }
}

// round 5
// speedup vs baseline: 2.8478x; 1.0678x over previous
#include <cuda_runtime.h>
#include <cuda_fp16.h>
#include <math.h>
#include <stdint.h>

// Problem constants
#define BATCH 32
#define TT    128          // time steps
#define HH    512          // hidden
#define VV    32000        // vocab
#define MM    (BATCH*TT)   // 4096 rows
#define G3H   (3*HH)       // 1536

// Logits GEMM (plain fp16) tiling
#define GBM 128
#define GBN 128
#define GBK 32
#define AKT 512            // A = Ah only (fp16)
#define BKT 512            // B = Bh only (fp16)
#define GNC (AKT/GBK)      // 16 chunks
#define PITCH 80           // smem row pitch bytes (64B data + 16B pad)
#define ABYTES (GBM*PITCH)
#define BBYTES (GBN*PITCH)
#define BUFBYTES (ABYTES+BBYTES)

#define SCAN_CTAS 128

// ---------------- device scratch (static, no allocation) ----------------
__device__ __align__(256) float g_x [MM * HH];        // gathered embeddings
__device__ __align__(256) float g_xg[MM * G3H];       // input gate preact
__device__ __align__(256) float g_h [2 * BATCH * HH]; // double-buffered hidden
__device__ __align__(256) __half g_a2[MM * AKT];      // fp16 hidden states
__device__ __align__(256) __half g_b2[VV * BKT];      // fp16 emb
__device__ unsigned g_bar_cnt;
__device__ unsigned g_bar_gen;

// =============================== PTX helpers ===============================
__device__ __forceinline__ uint32_t smem_u32(const void* p) {
    uint32_t r;
    asm("{ .reg .u64 t; cvta.to.shared.u64 t, %1; cvt.u32.u64 %0, t; }"
        : "=r"(r) : "l"(p));
    return r;
}
__device__ __forceinline__ void cp_async16(uint32_t dst, const void* src) {
    asm volatile("cp.async.cg.shared.global [%0], [%1], 16;\n"
                 :: "r"(dst), "l"(src));
}
__device__ __forceinline__ void cp_async_commit() {
    asm volatile("cp.async.commit_group;\n" ::: "memory");
}
__device__ __forceinline__ void cp_async_wait_all() {
    asm volatile("cp.async.wait_group 0;\n" ::: "memory");
}
__device__ __forceinline__ void ldsm_x4(uint32_t* r, uint32_t addr) {
    asm volatile("ldmatrix.sync.aligned.m8n8.x4.shared.b16 {%0,%1,%2,%3}, [%4];\n"
                 : "=r"(r[0]), "=r"(r[1]), "=r"(r[2]), "=r"(r[3]) : "r"(addr));
}
__device__ __forceinline__ void mma16816(float* c, const uint32_t* a, const uint32_t* b) {
    asm volatile(
        "mma.sync.aligned.m16n8k16.row.col.f32.f16.f16.f32 "
        "{%0,%1,%2,%3}, {%4,%5,%6,%7}, {%8,%9}, {%0,%1,%2,%3};\n"
        : "+f"(c[0]), "+f"(c[1]), "+f"(c[2]), "+f"(c[3])
        : "r"(a[0]), "r"(a[1]), "r"(a[2]), "r"(a[3]), "r"(b[0]), "r"(b[1]));
}

// ---------------- kernel 1: teacher-forced embedding gather ----------------
__global__ void gather_kernel(const float* __restrict__ emb,
                              const int* __restrict__ target,
                              float* __restrict__ x)
{
    int m = blockIdx.x;
    int b = m / TT;
    int t = m % TT;
    int tok = (t == 0) ? 1 : target[b * TT + t - 1];
    const float4* src = reinterpret_cast<const float4*>(emb + (size_t)tok * HH);
    float4* dst = reinterpret_cast<float4*>(x + (size_t)m * HH);
    dst[threadIdx.x] = src[threadIdx.x];
}

// ---------------- kernel 2: fp32 SGEMM (for xg)  C = A*B^T + bias ----------
#define BM 128
#define BN 128
#define BK 16

__global__ void __launch_bounds__(256)
sgemm_nt_bias(const float* __restrict__ A,
              const float* __restrict__ B,
              const float* __restrict__ bias,
              float* __restrict__ C,
              int M, int N, int K)
{
    __shared__ float As[BK][BM];
    __shared__ float Bs[BK][BN];

    int tid = threadIdx.x;
    int m0 = blockIdx.y * BM;
    int n0 = blockIdx.x * BN;

    int tm = (tid >> 4) * 8;
    int tn = (tid & 15) * 8;

    float acc[8][8];
#pragma unroll
    for (int i = 0; i < 8; ++i)
#pragma unroll
        for (int j = 0; j < 8; ++j) acc[i][j] = 0.f;

    for (int k0 = 0; k0 < K; k0 += BK) {
#pragma unroll
        for (int r = 0; r < 2; ++r) {
            int id  = tid + r * 256;
            int row = id >> 2;
            int c4  = id & 3;
            float4 va = *reinterpret_cast<const float4*>(
                A + (size_t)(m0 + row) * K + k0 + c4 * 4);
            As[c4*4+0][row] = va.x; As[c4*4+1][row] = va.y;
            As[c4*4+2][row] = va.z; As[c4*4+3][row] = va.w;
            float4 vb = *reinterpret_cast<const float4*>(
                B + (size_t)(n0 + row) * K + k0 + c4 * 4);
            Bs[c4*4+0][row] = vb.x; Bs[c4*4+1][row] = vb.y;
            Bs[c4*4+2][row] = vb.z; Bs[c4*4+3][row] = vb.w;
        }
        __syncthreads();

#pragma unroll
        for (int kk = 0; kk < BK; ++kk) {
            float a[8], bb[8];
            *reinterpret_cast<float4*>(&a[0])  = *reinterpret_cast<float4*>(&As[kk][tm]);
            *reinterpret_cast<float4*>(&a[4])  = *reinterpret_cast<float4*>(&As[kk][tm+4]);
            *reinterpret_cast<float4*>(&bb[0]) = *reinterpret_cast<float4*>(&Bs[kk][tn]);
            *reinterpret_cast<float4*>(&bb[4]) = *reinterpret_cast<float4*>(&Bs[kk][tn+4]);
#pragma unroll
            for (int i = 0; i < 8; ++i)
#pragma unroll
                for (int j = 0; j < 8; ++j)
                    acc[i][j] = fmaf(a[i], bb[j], acc[i][j]);
        }
        __syncthreads();
    }

    float bv[8];
#pragma unroll
    for (int j = 0; j < 8; ++j) bv[j] = bias[n0 + tn + j];

#pragma unroll
    for (int i = 0; i < 8; ++i) {
        float4 o0, o1;
        o0.x = acc[i][0] + bv[0]; o0.y = acc[i][1] + bv[1];
        o0.z = acc[i][2] + bv[2]; o0.w = acc[i][3] + bv[3];
        o1.x = acc[i][4] + bv[4]; o1.y = acc[i][5] + bv[5];
        o1.z = acc[i][6] + bv[6]; o1.w = acc[i][7] + bv[7];
        float* cp = C + (size_t)(m0 + tm + i) * N + n0 + tn;
        *reinterpret_cast<float4*>(cp)     = o0;
        *reinterpret_cast<float4*>(cp + 4) = o1;
    }
}

// ---------------- kernel 3: persistent GRU scan ----------------
__device__ __forceinline__ float sigmoidf_(float x) {
    return 1.0f / (1.0f + expf(-x));
}

__device__ __forceinline__ void grid_barrier() {
    __syncthreads();
    if (threadIdx.x == 0) {
        __threadfence();
        unsigned gen = *((volatile unsigned*)&g_bar_gen);
        if (atomicAdd(&g_bar_cnt, 1u) == SCAN_CTAS - 1) {
            *((volatile unsigned*)&g_bar_cnt) = 0;
            __threadfence();
            atomicAdd(&g_bar_gen, 1u);
        } else {
            while (*((volatile unsigned*)&g_bar_gen) == gen) { }
        }
        __threadfence();
    }
    __syncthreads();
}

// grid 128 CTAs x 256 threads; CTA owns 4 hidden indices for all 32 batches.
__global__ void __launch_bounds__(256)
gru_scan_kernel(const float* __restrict__ enc,
                const float* __restrict__ xg,
                const float* __restrict__ w_hh,
                const float* __restrict__ b_hh,
                __half* __restrict__ a2,
                float* __restrict__ hbuf)
{
    extern __shared__ float sm[];
    float* w_s = sm;                  // 6144 floats
    float* h_T = sm + 6144;           // 16896 floats
    float* red = sm + 6144 + 16896;   // 384 floats

    const int tid  = threadIdx.x;
    const int lane = tid & 31;
    const int w    = tid >> 5;
    const int il   = w & 3;
    const int kh   = w >> 2;
    const int i0   = blockIdx.x * 4;
    const int i    = i0 + il;

    // load this CTA's 12 w_hh rows (gate-major) into smem
#pragma unroll
    for (int j = 0; j < 6; ++j) {
        int f   = tid + j * 256;       // float4 index 0..1535
        int row = f >> 7;              // 0..11
        int q   = f & 127;
        int g   = row >> 2, ii = row & 3;
        float4 v = *reinterpret_cast<const float4*>(
            w_hh + (size_t)(g * HH + i0 + ii) * HH + q * 4);
        *reinterpret_cast<float4*>(w_s + (size_t)row * HH + q * 4) = v;
    }
    const float br = b_hh[i];
    const float bz = b_hh[i + HH];
    const float bn = b_hh[i + 2*HH];

    const int lb = tid >> 3, lq = tid & 7;

    for (int t = 0; t < TT; ++t) {
        const float* hp = (t == 0) ? enc
                                   : hbuf + (size_t)(t & 1) * BATCH * HH;
        // stage h transposed into smem: h_T[k][b]
#pragma unroll
        for (int j = 0; j < 16; ++j) {
            int k4 = (lq + j * 8) * 4;
            float4 v = *reinterpret_cast<const float4*>(hp + (size_t)lb * HH + k4);
            h_T[(k4+0)*33 + lb] = v.x;
            h_T[(k4+1)*33 + lb] = v.y;
            h_T[(k4+2)*33 + lb] = v.z;
            h_T[(k4+3)*33 + lb] = v.w;
        }
        __syncthreads();

        float accr = 0.f, accz = 0.f, accn = 0.f;
        {
            const float4* wr4 = reinterpret_cast<const float4*>(w_s + (0*4+il)*HH) + kh*64;
            const float4* wz4 = reinterpret_cast<const float4*>(w_s + (1*4+il)*HH) + kh*64;
            const float4* wn4 = reinterpret_cast<const float4*>(w_s + (2*4+il)*HH) + kh*64;
            const float* hb = h_T + (size_t)(kh*256)*33 + lane;
#pragma unroll 8
            for (int k4 = 0; k4 < 64; ++k4) {
                float4 a = wr4[k4], d = wz4[k4], e = wn4[k4];
                const float* hq = hb + k4*4*33;
                float h0 = hq[0], h1 = hq[33], h2 = hq[66], h3 = hq[99];
                accr = fmaf(a.x,h0,accr); accr = fmaf(a.y,h1,accr);
                accr = fmaf(a.z,h2,accr); accr = fmaf(a.w,h3,accr);
                accz = fmaf(d.x,h0,accz); accz = fmaf(d.y,h1,accz);
                accz = fmaf(d.z,h2,accz); accz = fmaf(d.w,h3,accz);
                accn = fmaf(e.x,h0,accn); accn = fmaf(e.y,h1,accn);
                accn = fmaf(e.z,h2,accn); accn = fmaf(e.w,h3,accn);
            }
        }
        if (kh == 1) {
            red[(il*3+0)*32 + lane] = accr;
            red[(il*3+1)*32 + lane] = accz;
            red[(il*3+2)*32 + lane] = accn;
        }
        __syncthreads();
        if (kh == 0) {
            accr += red[(il*3+0)*32 + lane];
            accz += red[(il*3+1)*32 + lane];
            accn += red[(il*3+2)*32 + lane];

            int b = lane;
            size_t mrow = (size_t)b * TT + t;
            const float* xgp = xg + mrow * G3H;
            float r  = sigmoidf_(xgp[i]        + accr + br);
            float z  = sigmoidf_(xgp[i +   HH] + accz + bz);
            float hn = accn + bn;
            float n  = tanhf(xgp[i + 2*HH] + r * hn);
            float hprev = h_T[i*33 + b];
            float hnew = (1.0f - z) * n + z * hprev;

            hbuf[(size_t)((t+1)&1)*BATCH*HH + (size_t)b*HH + i] = hnew;
            a2[mrow * AKT + i] = __float2half(hnew);
        }
        grid_barrier();
    }
}

// ---------------- kernel 4: emb -> fp16 Bh (K=512) ----------------
__global__ void __launch_bounds__(128)
split_emb_kernel(const float* __restrict__ emb, __half* __restrict__ b2)
{
    int row = blockIdx.x;              // 0..31999
    const float* src = emb + (size_t)row * HH;
    __half* dst = b2 + (size_t)row * BKT;
#pragma unroll
    for (int j = 0; j < 4; ++j) {
        int k = threadIdx.x + j * 128;
        dst[k] = __float2half(src[k]);
    }
}

// ---------------- kernel 5: fp16 mma.sync GEMM (logits), K=512 --------------
// C[4096,32000] = A[4096,512] * B[32000,512]^T + bias, fp32 accumulate.
__device__ __forceinline__ void gemm_load_tile(
    uint32_t sa, uint32_t sbm, int m0, int n0, int chunk, int tid,
    const __half* __restrict__ A, const __half* __restrict__ B)
{
#pragma unroll
    for (int r = 0; r < 2; ++r) {
        int c = tid + r * 256;
        int row = c >> 2;
        int q   = c & 3;
        cp_async16(sa + row * PITCH + q * 16,
                   A + (size_t)(m0 + row) * AKT + chunk * GBK + q * 8);
    }
#pragma unroll
    for (int r = 0; r < 2; ++r) {
        int c = tid + r * 256;
        int row = c >> 2;
        int q   = c & 3;
        cp_async16(sbm + row * PITCH + q * 16,
                   B + (size_t)(n0 + row) * BKT + chunk * GBK + q * 8);
    }
    cp_async_commit();
}

__global__ void __launch_bounds__(256)
gemm_fp16_mma(const __half* __restrict__ A,
              const __half* __restrict__ B,
              const float* __restrict__ bias,
              float* __restrict__ C)
{
    __shared__ __align__(128) char smem[2 * BUFBYTES];

    const int tid  = threadIdx.x;
    const int lane = tid & 31;
    const int wid  = tid >> 5;
    const int wm   = wid & 3;
    const int wn   = wid >> 2;
    const int m0 = blockIdx.x * GBM;   // 32 m-tiles (fast dim -> A L2 reuse)
    const int n0 = blockIdx.y * GBN;   // 250 n-tiles

    const uint32_t sb = smem_u32(smem);

    float acc[2][8][4];
#pragma unroll
    for (int i = 0; i < 2; ++i)
#pragma unroll
        for (int j = 0; j < 8; ++j)
#pragma unroll
            for (int k = 0; k < 4; ++k) acc[i][j][k] = 0.f;

    gemm_load_tile(sb, sb + ABYTES, m0, n0, 0, tid, A, B);

    const uint32_t a_lane_off = (uint32_t)(lane & 15) * PITCH + (uint32_t)(lane >> 4) * 16;
    const uint32_t b_lane_off = (uint32_t)(lane & 7)  * PITCH + (uint32_t)(lane >> 3) * 16;

    for (int c = 0; c < GNC; ++c) {
        int cur = c & 1;
        uint32_t sa  = sb + cur * BUFBYTES;
        uint32_t sbm = sa + ABYTES;

        cp_async_wait_all();
        __syncthreads();

        if (c + 1 < GNC) {
            int nxt = (c + 1) & 1;
            gemm_load_tile(sb + nxt * BUFBYTES, sb + nxt * BUFBYTES + ABYTES,
                           m0, n0, c + 1, tid, A, B);
        }

        uint32_t bf[8][4];
#pragma unroll
        for (int nt = 0; nt < 8; ++nt) {
            uint32_t addr = sbm + (uint32_t)(wn * 64 + nt * 8) * PITCH + b_lane_off;
            ldsm_x4(bf[nt], addr);
        }

#pragma unroll
        for (int ks = 0; ks < 2; ++ks) {
#pragma unroll
            for (int mt = 0; mt < 2; ++mt) {
                uint32_t af[4];
                uint32_t addr = sa + (uint32_t)(wm * 32 + mt * 16) * PITCH
                                + (uint32_t)(ks * 2) * 16 + a_lane_off;
                ldsm_x4(af, addr);
#pragma unroll
                for (int nt = 0; nt < 8; ++nt)
                    mma16816(acc[mt][nt], af, &bf[nt][ks * 2]);
            }
        }
        __syncthreads();
    }

    const int col_base = n0 + wn * 64 + 2 * (lane & 3);
    const int row_base = m0 + wm * 32 + (lane >> 2);
#pragma unroll
    for (int mt = 0; mt < 2; ++mt) {
#pragma unroll
        for (int half = 0; half < 2; ++half) {
            int row = row_base + mt * 16 + half * 8;
            float* cr = C + (size_t)row * VV;
#pragma unroll
            for (int nt = 0; nt < 8; ++nt) {
                int col = col_base + nt * 8;
                float2 o;
                o.x = acc[mt][nt][half * 2 + 0] + bias[col];
                o.y = acc[mt][nt][half * 2 + 1] + bias[col + 1];
                *reinterpret_cast<float2*>(cr + col) = o;
            }
        }
    }
}

// ---------------- launcher ----------------
extern "C" void kernel_launch(void* const* d_in, const int* in_sizes, int n_in,
                              void* d_out, int out_size)
{
    const float* emb    = (const float*)d_in[0];   // [32000,512]
    const float* w_ih   = (const float*)d_in[1];   // [1536,512]
    const float* w_hh   = (const float*)d_in[2];   // [1536,512]
    const float* b_ih   = (const float*)d_in[3];   // [1536]
    const float* b_hh   = (const float*)d_in[4];   // [1536]
    const float* b_out  = (const float*)d_in[5];   // [32000]
    const float* enc    = (const float*)d_in[6];   // [1,32,512]
    const int*   target = (const int*)  d_in[7];   // [32,128]
    float* out = (float*)d_out;                    // [32,128,32000]

    float *px, *pxg, *ph;
    __half *pa2, *pb2;
    cudaGetSymbolAddress((void**)&px,  g_x);
    cudaGetSymbolAddress((void**)&pxg, g_xg);
    cudaGetSymbolAddress((void**)&ph,  g_h);
    cudaGetSymbolAddress((void**)&pa2, g_a2);
    cudaGetSymbolAddress((void**)&pb2, g_b2);

    const int scan_smem = (6144 + 16896 + 384) * 4;   // 93696 B
    cudaFuncSetAttribute(gru_scan_kernel,
                         cudaFuncAttributeMaxDynamicSharedMemorySize, scan_smem);

    // 1) gather teacher-forced embeddings
    gather_kernel<<<MM, 128>>>(emb, target, px);

    // 1b) emb -> fp16 Bh
    split_emb_kernel<<<VV, 128>>>(emb, pb2);

    // 2) xg = x @ w_ih^T + b_ih   [4096,1536]  (fp32)
    {
        dim3 grid(G3H / BN, MM / BM);
        sgemm_nt_bias<<<grid, 256>>>(px, w_ih, b_ih, pxg, MM, G3H, HH);
    }

    // 3) persistent GRU scan (writes fp16 h directly)
    gru_scan_kernel<<<SCAN_CTAS, 256, scan_smem>>>(enc, pxg, w_hh, b_hh, pa2, ph);

    // 4) logits = hs @ emb^T + b_out via fp16 mma GEMM (K=512)
    {
        dim3 grid(MM / GBM, VV / GBN);   // (32, 250)
        gemm_fp16_mma<<<grid, 256>>>(pa2, pb2, b_out, out);
    }
}